// round 1
// baseline (speedup 1.0000x reference)
#include <cuda_runtime.h>
#include <math.h>

#define D_  768
#define H_  12
#define HD_ 64
#define FF_ 3072
#define B_  8
#define N_  1024
#define M_  (B_*N_)          // 8192 rows
#define SCALING_ 0.125f      // HD^-0.5
#define EPS_ 1e-5f

// ---------------- scratch (static device globals; no allocation) -------------
__device__ float g_h  [M_*D_];   // LN1 out, reused as LN2 out
__device__ float g_q  [M_*D_];
__device__ float g_k  [M_*D_];
__device__ float g_v  [M_*D_];
__device__ float g_att[M_*D_];
__device__ float g_ff [M_*FF_];

// ---------------- LayerNorm: one block per row -------------------------------
__global__ __launch_bounds__(256)
void ln_kernel(const float* __restrict__ x, const float* __restrict__ w,
               const float* __restrict__ b, float* __restrict__ out) {
    const int row = blockIdx.x;
    const int tid = threadIdx.x;
    const float* xr = x + (size_t)row * D_;
    float v[3];
    float s = 0.f;
    #pragma unroll
    for (int i = 0; i < 3; i++) { v[i] = xr[tid + i*256]; s += v[i]; }

    __shared__ float red[8];
    __shared__ float bc[2];
    // warp reduce
    #pragma unroll
    for (int o = 16; o; o >>= 1) s += __shfl_xor_sync(0xffffffffu, s, o);
    if ((tid & 31) == 0) red[tid >> 5] = s;
    __syncthreads();
    if (tid == 0) {
        float t = 0.f;
        #pragma unroll
        for (int i = 0; i < 8; i++) t += red[i];
        bc[0] = t * (1.0f / D_);
    }
    __syncthreads();
    const float mu = bc[0];

    float s2 = 0.f;
    #pragma unroll
    for (int i = 0; i < 3; i++) { float d = v[i] - mu; s2 += d * d; }
    #pragma unroll
    for (int o = 16; o; o >>= 1) s2 += __shfl_xor_sync(0xffffffffu, s2, o);
    if ((tid & 31) == 0) red[tid >> 5] = s2;
    __syncthreads();
    if (tid == 0) {
        float t = 0.f;
        #pragma unroll
        for (int i = 0; i < 8; i++) t += red[i];
        bc[1] = rsqrtf(t * (1.0f / D_) + EPS_);
    }
    __syncthreads();
    const float rstd = bc[1];

    float* orow = out + (size_t)row * D_;
    #pragma unroll
    for (int i = 0; i < 3; i++) {
        int c = tid + i*256;
        orow[c] = (v[i] - mu) * rstd * w[c] + b[c];
    }
}

// ---------------- fp32 NT GEMM: C[M,N] = A[M,K] @ W[N,K]^T + bias ------------
// EP: 0 = plain, 1 = *SCALING, 2 = exact GELU, 3 = + res[r,c]
template<int EP>
__global__ __launch_bounds__(256)
void gemm_nt(const float* __restrict__ A, const float* __restrict__ W,
             const float* __restrict__ bias, const float* __restrict__ res,
             float* __restrict__ C, int M, int N, int K) {
    __shared__ float As[8][128];
    __shared__ float Ws[8][128];
    const int tid = threadIdx.x;
    const int tx = tid & 15, ty = tid >> 4;
    const int m0 = blockIdx.y << 7, n0 = blockIdx.x << 7;

    const int lr = tid >> 1;          // 0..127
    const int lk = (tid & 1) << 2;    // 0 or 4
    const float* Ap = A + (size_t)(m0 + lr) * K + lk;
    const float* Wp = W + (size_t)(n0 + lr) * K + lk;

    float acc[8][8];
    #pragma unroll
    for (int i = 0; i < 8; i++)
        #pragma unroll
        for (int j = 0; j < 8; j++) acc[i][j] = 0.f;

    for (int kt = 0; kt < K; kt += 8) {
        float4 av = *(const float4*)(Ap + kt);
        float4 wv = *(const float4*)(Wp + kt);
        As[lk+0][lr] = av.x; As[lk+1][lr] = av.y; As[lk+2][lr] = av.z; As[lk+3][lr] = av.w;
        Ws[lk+0][lr] = wv.x; Ws[lk+1][lr] = wv.y; Ws[lk+2][lr] = wv.z; Ws[lk+3][lr] = wv.w;
        __syncthreads();
        #pragma unroll
        for (int kk = 0; kk < 8; kk++) {
            float a[8], w[8];
            *(float4*)&a[0] = *(const float4*)&As[kk][ty << 3];
            *(float4*)&a[4] = *(const float4*)&As[kk][(ty << 3) + 4];
            *(float4*)&w[0] = *(const float4*)&Ws[kk][tx << 3];
            *(float4*)&w[4] = *(const float4*)&Ws[kk][(tx << 3) + 4];
            #pragma unroll
            for (int i = 0; i < 8; i++)
                #pragma unroll
                for (int j = 0; j < 8; j++)
                    acc[i][j] = fmaf(a[i], w[j], acc[i][j]);
        }
        __syncthreads();
    }

    #pragma unroll
    for (int i = 0; i < 8; i++) {
        const int r = m0 + (ty << 3) + i;
        #pragma unroll
        for (int j = 0; j < 8; j++) {
            const int c = n0 + (tx << 3) + j;
            float val = acc[i][j] + bias[c];
            if (EP == 1) val *= SCALING_;
            if (EP == 2) val = 0.5f * val * (1.0f + erff(val * 0.70710678118654752f));
            if (EP == 3) val += res[(size_t)r * N + c];
            C[(size_t)r * N + c] = val;
        }
    }
}

// ---------------- RoPE (interleaved pairs), in-place -------------------------
__global__ void rope_kernel(float* __restrict__ t, const float* __restrict__ freqs, int npairs) {
    int idx = blockIdx.x * blockDim.x + threadIdx.x;
    if (idx >= npairs) return;
    const int row = idx / (D_ / 2);
    const int p   = idx - row * (D_ / 2);   // pair index within row
    const int i   = p & 31;                 // freq index within head (HD/2=32)
    const int n   = row & (N_ - 1);         // sequence position
    const float ang = (float)n * freqs[i];
    const float c = cosf(ang), s = sinf(ang);
    float* base = t + (size_t)row * D_ + p * 2;
    const float x0 = base[0], x1 = base[1];
    base[0] = x0 * c - x1 * s;
    base[1] = x1 * c + x0 * s;
}

// ---------------- flash attention, fp32, BQ=64 BK=32 -------------------------
__device__ __forceinline__ float rmax16(float v) {
    #pragma unroll
    for (int o = 8; o; o >>= 1) v = fmaxf(v, __shfl_xor_sync(0xffffffffu, v, o, 16));
    return v;
}
__device__ __forceinline__ float rsum16(float v) {
    #pragma unroll
    for (int o = 8; o; o >>= 1) v += __shfl_xor_sync(0xffffffffu, v, o, 16);
    return v;
}

__global__ __launch_bounds__(256)
void attn_kernel(const float* __restrict__ q, const float* __restrict__ k,
                 const float* __restrict__ v, const unsigned char* __restrict__ pm,
                 float* __restrict__ out) {
    __shared__ float Qs[64][65];     // [d][r]
    __shared__ float Ks[64][33];     // [d][c]
    __shared__ float Vs[32][68];     // [c][d] (pad 4 keeps float4 alignment)
    __shared__ float Ps[64][33];     // [r][c]
    __shared__ unsigned char Ms[32];

    const int tid = threadIdx.x;
    const int tx = tid & 15, ty = tid >> 4;
    const int qt = blockIdx.x, bh = blockIdx.y;
    const int b = bh / H_, h = bh - b * H_;
    const int row0 = b * N_ + qt * 64;
    const int colh = h * HD_;

    // load Q tile, transposed to [d][r]
    for (int idx = tid; idx < 64 * 64; idx += 256) {
        const int r = idx >> 6, d = idx & 63;
        Qs[d][r] = q[(size_t)(row0 + r) * D_ + colh + d];
    }

    float o[4][4];
    #pragma unroll
    for (int i = 0; i < 4; i++)
        #pragma unroll
        for (int j = 0; j < 4; j++) o[i][j] = 0.f;
    float mreg[4], lreg[4];
    #pragma unroll
    for (int i = 0; i < 4; i++) { mreg[i] = -3.0e38f; lreg[i] = 0.f; }

    const int r0  = ty << 2;   // query row base within tile
    const int c0s = tx << 1;   // key col base for S (32 wide)
    const int c0o = tx << 2;   // dim col base for O (64 wide)

    for (int kt = 0; kt < N_; kt += 32) {
        for (int idx = tid; idx < 32 * 64; idx += 256) {
            const int c = idx >> 6, d = idx & 63;
            const size_t g = (size_t)(b * N_ + kt + c) * D_ + colh + d;
            Ks[d][c] = k[g];
            Vs[c][d] = v[g];
        }
        if (tid < 32) Ms[tid] = pm[b * N_ + kt + tid];
        __syncthreads();

        // S = Q K^T  (4x2 per thread)
        float s[4][2];
        s[0][0]=s[0][1]=s[1][0]=s[1][1]=s[2][0]=s[2][1]=s[3][0]=s[3][1]=0.f;
        #pragma unroll 4
        for (int d = 0; d < 64; d++) {
            const float a0 = Qs[d][r0], a1 = Qs[d][r0+1], a2 = Qs[d][r0+2], a3 = Qs[d][r0+3];
            const float b0 = Ks[d][c0s], b1 = Ks[d][c0s+1];
            s[0][0] = fmaf(a0, b0, s[0][0]); s[0][1] = fmaf(a0, b1, s[0][1]);
            s[1][0] = fmaf(a1, b0, s[1][0]); s[1][1] = fmaf(a1, b1, s[1][1]);
            s[2][0] = fmaf(a2, b0, s[2][0]); s[2][1] = fmaf(a2, b1, s[2][1]);
            s[3][0] = fmaf(a3, b0, s[3][0]); s[3][1] = fmaf(a3, b1, s[3][1]);
        }
        const bool msk0 = Ms[c0s] != 0, msk1 = Ms[c0s+1] != 0;
        #pragma unroll
        for (int i = 0; i < 4; i++) {
            s[i][0] = msk0 ? -3.0e38f : s[i][0] * 0.125f;
            s[i][1] = msk1 ? -3.0e38f : s[i][1] * 0.125f;
        }

        // online softmax per row
        #pragma unroll
        for (int i = 0; i < 4; i++) {
            float mt = rmax16(fmaxf(s[i][0], s[i][1]));
            const float mnew = fmaxf(mreg[i], mt);
            const float alpha = __expf(mreg[i] - mnew);
            const float p0 = __expf(s[i][0] - mnew);
            const float p1 = __expf(s[i][1] - mnew);
            const float rs = rsum16(p0 + p1);
            lreg[i] = lreg[i] * alpha + rs;
            mreg[i] = mnew;
            #pragma unroll
            for (int j = 0; j < 4; j++) o[i][j] *= alpha;
            Ps[r0 + i][c0s]     = p0;
            Ps[r0 + i][c0s + 1] = p1;
        }
        __syncthreads();

        // O += P V   (4x4 per thread)
        #pragma unroll 4
        for (int kk = 0; kk < 32; kk++) {
            const float4 vv = *(const float4*)&Vs[kk][c0o];
            const float p0 = Ps[r0][kk],   p1 = Ps[r0+1][kk];
            const float p2 = Ps[r0+2][kk], p3 = Ps[r0+3][kk];
            o[0][0] = fmaf(p0, vv.x, o[0][0]); o[0][1] = fmaf(p0, vv.y, o[0][1]);
            o[0][2] = fmaf(p0, vv.z, o[0][2]); o[0][3] = fmaf(p0, vv.w, o[0][3]);
            o[1][0] = fmaf(p1, vv.x, o[1][0]); o[1][1] = fmaf(p1, vv.y, o[1][1]);
            o[1][2] = fmaf(p1, vv.z, o[1][2]); o[1][3] = fmaf(p1, vv.w, o[1][3]);
            o[2][0] = fmaf(p2, vv.x, o[2][0]); o[2][1] = fmaf(p2, vv.y, o[2][1]);
            o[2][2] = fmaf(p2, vv.z, o[2][2]); o[2][3] = fmaf(p2, vv.w, o[2][3]);
            o[3][0] = fmaf(p3, vv.x, o[3][0]); o[3][1] = fmaf(p3, vv.y, o[3][1]);
            o[3][2] = fmaf(p3, vv.z, o[3][2]); o[3][3] = fmaf(p3, vv.w, o[3][3]);
        }
        __syncthreads();
    }

    #pragma unroll
    for (int i = 0; i < 4; i++) {
        const float inv = 1.0f / lreg[i];
        float4 r4;
        r4.x = o[i][0] * inv; r4.y = o[i][1] * inv;
        r4.z = o[i][2] * inv; r4.w = o[i][3] * inv;
        *(float4*)&out[(size_t)(row0 + r0 + i) * D_ + colh + c0o] = r4;
    }
}

// ---------------- launch ------------------------------------------------------
extern "C" void kernel_launch(void* const* d_in, const int* in_sizes, int n_in,
                              void* d_out, int out_size) {
    const float* x     = (const float*)d_in[0];
    const unsigned char* pmask = (const unsigned char*)d_in[1];
    const float* wq = (const float*)d_in[2];
    const float* bq = (const float*)d_in[3];
    const float* wk = (const float*)d_in[4];
    const float* bk = (const float*)d_in[5];
    const float* wv = (const float*)d_in[6];
    const float* bv = (const float*)d_in[7];
    const float* wo = (const float*)d_in[8];
    const float* bo = (const float*)d_in[9];
    const float* w1 = (const float*)d_in[10];
    const float* b1 = (const float*)d_in[11];
    const float* w2 = (const float*)d_in[12];
    const float* b2 = (const float*)d_in[13];
    const float* ln1w = (const float*)d_in[14];
    const float* ln1b = (const float*)d_in[15];
    const float* ln2w = (const float*)d_in[16];
    const float* ln2b = (const float*)d_in[17];
    const float* freqs = (const float*)d_in[18];
    float* out = (float*)d_out;

    float *ph, *pq, *pk, *pv, *patt, *pff;
    cudaGetSymbolAddress((void**)&ph,   g_h);
    cudaGetSymbolAddress((void**)&pq,   g_q);
    cudaGetSymbolAddress((void**)&pk,   g_k);
    cudaGetSymbolAddress((void**)&pv,   g_v);
    cudaGetSymbolAddress((void**)&patt, g_att);
    cudaGetSymbolAddress((void**)&pff,  g_ff);

    const dim3 gD(D_ / 128, M_ / 128);     // (6, 64)
    const dim3 gF(FF_ / 128, M_ / 128);    // (24, 64)

    // LN1
    ln_kernel<<<M_, 256>>>(x, ln1w, ln1b, ph);
    // QKV projections
    gemm_nt<1><<<gD, 256>>>(ph, wq, bq, nullptr, pq, M_, D_, D_);
    gemm_nt<0><<<gD, 256>>>(ph, wk, bk, nullptr, pk, M_, D_, D_);
    gemm_nt<0><<<gD, 256>>>(ph, wv, bv, nullptr, pv, M_, D_, D_);
    // RoPE on q and k
    const int npairs = M_ * (D_ / 2);
    rope_kernel<<<(npairs + 255) / 256, 256>>>(pq, freqs, npairs);
    rope_kernel<<<(npairs + 255) / 256, 256>>>(pk, freqs, npairs);
    // attention
    attn_kernel<<<dim3(N_ / 64, B_ * H_), 256>>>(pq, pk, pv, pmask, patt);
    // O projection + residual (x) -> d_out
    gemm_nt<3><<<gD, 256>>>(patt, wo, bo, x, out, M_, D_, D_);
    // LN2 (reuse g_h)
    ln_kernel<<<M_, 256>>>(out, ln2w, ln2b, ph);
    // FFN1 with exact GELU
    gemm_nt<2><<<gF, 256>>>(ph, w1, b1, nullptr, pff, M_, FF_, D_);
    // FFN2 + residual (d_out) -> d_out (in-place safe: each element read/written once)
    gemm_nt<3><<<gD, 256>>>(pff, w2, b2, out, out, M_, D_, FF_);
}

// round 2
// speedup vs baseline: 1.9521x; 1.9521x over previous
#include <cuda_runtime.h>
#include <math.h>

#define D_  768
#define H_  12
#define HD_ 64
#define FF_ 3072
#define B_  8
#define N_  1024
#define M_  (B_*N_)          // 8192 rows
#define SCALING_ 0.125f      // HD^-0.5
#define EPS_ 1e-5f

// ---------------- scratch (static device globals; no allocation) -------------
__device__ float g_h  [M_*D_];   // LN1 out, reused as LN2 out
__device__ float g_q  [M_*D_];
__device__ float g_k  [M_*D_];
__device__ float g_v  [M_*D_];
__device__ float g_att[M_*D_];
__device__ float g_ff [M_*FF_];

// ---------------- LayerNorm: one block per row -------------------------------
__global__ __launch_bounds__(256)
void ln_kernel(const float* __restrict__ x, const float* __restrict__ w,
               const float* __restrict__ b, float* __restrict__ out) {
    const int row = blockIdx.x;
    const int tid = threadIdx.x;
    const float* xr = x + (size_t)row * D_;
    float v[3];
    float s = 0.f;
    #pragma unroll
    for (int i = 0; i < 3; i++) { v[i] = xr[tid + i*256]; s += v[i]; }

    __shared__ float red[8];
    __shared__ float bc[2];
    #pragma unroll
    for (int o = 16; o; o >>= 1) s += __shfl_xor_sync(0xffffffffu, s, o);
    if ((tid & 31) == 0) red[tid >> 5] = s;
    __syncthreads();
    if (tid == 0) {
        float t = 0.f;
        #pragma unroll
        for (int i = 0; i < 8; i++) t += red[i];
        bc[0] = t * (1.0f / D_);
    }
    __syncthreads();
    const float mu = bc[0];

    float s2 = 0.f;
    #pragma unroll
    for (int i = 0; i < 3; i++) { float d = v[i] - mu; s2 += d * d; }
    #pragma unroll
    for (int o = 16; o; o >>= 1) s2 += __shfl_xor_sync(0xffffffffu, s2, o);
    if ((tid & 31) == 0) red[tid >> 5] = s2;
    __syncthreads();
    if (tid == 0) {
        float t = 0.f;
        #pragma unroll
        for (int i = 0; i < 8; i++) t += red[i];
        bc[1] = rsqrtf(t * (1.0f / D_) + EPS_);
    }
    __syncthreads();
    const float rstd = bc[1];

    float* orow = out + (size_t)row * D_;
    #pragma unroll
    for (int i = 0; i < 3; i++) {
        int c = tid + i*256;
        orow[c] = (v[i] - mu) * rstd * w[c] + b[c];
    }
}

// ---------------- tf32 helpers -----------------------------------------------
__device__ __forceinline__ unsigned f2tf32(float f) {
    unsigned r;
    asm("cvt.rna.tf32.f32 %0, %1;" : "=r"(r) : "f"(f));
    return r;
}

__device__ __forceinline__ void mma_tf32(float& c0, float& c1, float& c2, float& c3,
                                         unsigned a0, unsigned a1, unsigned a2, unsigned a3,
                                         unsigned b0, unsigned b1) {
    asm volatile(
        "mma.sync.aligned.m16n8k8.row.col.f32.tf32.tf32.f32 "
        "{%0,%1,%2,%3}, {%4,%5,%6,%7}, {%8,%9}, {%0,%1,%2,%3};"
        : "+f"(c0), "+f"(c1), "+f"(c2), "+f"(c3)
        : "r"(a0), "r"(a1), "r"(a2), "r"(a3), "r"(b0), "r"(b1));
}

// ---------------- tf32 NT GEMM: C[M,N] = A[M,K] @ W[N,K]^T + bias ------------
// 128x128 CTA tile, 8 warps (2x4), warp tile 64x32, k-step 16, double buffered.
// EP: 0 = plain, 1 = *SCALING, 2 = exact GELU, 3 = + res[r,c]
#define KPAD 20
template<int EP>
__global__ __launch_bounds__(256, 1)
void gemm_tf32(const float* __restrict__ A, const float* __restrict__ W,
               const float* __restrict__ bias, const float* __restrict__ res,
               float* __restrict__ C, int M, int N, int K) {
    __shared__ unsigned As[2][128][KPAD];
    __shared__ unsigned Ws[2][128][KPAD];

    const int tid  = threadIdx.x;
    const int lane = tid & 31;
    const int warp = tid >> 5;
    const int wm = (warp >> 2) * 64;   // 0 or 64
    const int wn = (warp & 3) * 32;    // 0,32,64,96
    const int grp = lane >> 2;         // 0..7
    const int qk  = lane & 3;          // 0..3

    const int m0 = blockIdx.y << 7, n0 = blockIdx.x << 7;

    // global load mapping: each thread: rows (tid>>2) and (tid>>2)+64, 4 floats at col (tid&3)*4
    const int ldr = tid >> 2;
    const int ldc = (tid & 3) << 2;
    const float* Ap0 = A + (size_t)(m0 + ldr) * K + ldc;
    const float* Ap1 = A + (size_t)(m0 + ldr + 64) * K + ldc;
    const float* Wp0 = W + (size_t)(n0 + ldr) * K + ldc;
    const float* Wp1 = W + (size_t)(n0 + ldr + 64) * K + ldc;

    float acc[4][4][4];   // [mi][ni][frag]
    #pragma unroll
    for (int i = 0; i < 4; i++)
        #pragma unroll
        for (int j = 0; j < 4; j++)
            #pragma unroll
            for (int f = 0; f < 4; f++) acc[i][j][f] = 0.f;

    const int ntiles = K >> 4;

    // prologue: tile 0 -> buf 0
    {
        float4 a0 = *(const float4*)(Ap0);
        float4 a1 = *(const float4*)(Ap1);
        float4 w0 = *(const float4*)(Wp0);
        float4 w1 = *(const float4*)(Wp1);
        As[0][ldr   ][ldc+0]=f2tf32(a0.x); As[0][ldr   ][ldc+1]=f2tf32(a0.y);
        As[0][ldr   ][ldc+2]=f2tf32(a0.z); As[0][ldr   ][ldc+3]=f2tf32(a0.w);
        As[0][ldr+64][ldc+0]=f2tf32(a1.x); As[0][ldr+64][ldc+1]=f2tf32(a1.y);
        As[0][ldr+64][ldc+2]=f2tf32(a1.z); As[0][ldr+64][ldc+3]=f2tf32(a1.w);
        Ws[0][ldr   ][ldc+0]=f2tf32(w0.x); Ws[0][ldr   ][ldc+1]=f2tf32(w0.y);
        Ws[0][ldr   ][ldc+2]=f2tf32(w0.z); Ws[0][ldr   ][ldc+3]=f2tf32(w0.w);
        Ws[0][ldr+64][ldc+0]=f2tf32(w1.x); Ws[0][ldr+64][ldc+1]=f2tf32(w1.y);
        Ws[0][ldr+64][ldc+2]=f2tf32(w1.z); Ws[0][ldr+64][ldc+3]=f2tf32(w1.w);
    }
    __syncthreads();

    for (int it = 0; it < ntiles; it++) {
        const int cur = it & 1, nxt = cur ^ 1;
        float4 a0, a1, w0, w1;
        const bool have_next = (it + 1) < ntiles;
        if (have_next) {
            const int ko = (it + 1) << 4;
            a0 = *(const float4*)(Ap0 + ko);
            a1 = *(const float4*)(Ap1 + ko);
            w0 = *(const float4*)(Wp0 + ko);
            w1 = *(const float4*)(Wp1 + ko);
        }

        #pragma unroll
        for (int ks = 0; ks < 2; ks++) {
            const int k8 = ks << 3;
            unsigned af[4][4], bf[4][2];
            #pragma unroll
            for (int mi = 0; mi < 4; mi++) {
                const int m = wm + (mi << 4);
                af[mi][0] = As[cur][m + grp    ][k8 + qk];
                af[mi][1] = As[cur][m + grp + 8][k8 + qk];
                af[mi][2] = As[cur][m + grp    ][k8 + qk + 4];
                af[mi][3] = As[cur][m + grp + 8][k8 + qk + 4];
            }
            #pragma unroll
            for (int ni = 0; ni < 4; ni++) {
                const int n = wn + (ni << 3);
                bf[ni][0] = Ws[cur][n + grp][k8 + qk];
                bf[ni][1] = Ws[cur][n + grp][k8 + qk + 4];
            }
            #pragma unroll
            for (int mi = 0; mi < 4; mi++)
                #pragma unroll
                for (int ni = 0; ni < 4; ni++)
                    mma_tf32(acc[mi][ni][0], acc[mi][ni][1], acc[mi][ni][2], acc[mi][ni][3],
                             af[mi][0], af[mi][1], af[mi][2], af[mi][3],
                             bf[ni][0], bf[ni][1]);
        }

        if (have_next) {
            As[nxt][ldr   ][ldc+0]=f2tf32(a0.x); As[nxt][ldr   ][ldc+1]=f2tf32(a0.y);
            As[nxt][ldr   ][ldc+2]=f2tf32(a0.z); As[nxt][ldr   ][ldc+3]=f2tf32(a0.w);
            As[nxt][ldr+64][ldc+0]=f2tf32(a1.x); As[nxt][ldr+64][ldc+1]=f2tf32(a1.y);
            As[nxt][ldr+64][ldc+2]=f2tf32(a1.z); As[nxt][ldr+64][ldc+3]=f2tf32(a1.w);
            Ws[nxt][ldr   ][ldc+0]=f2tf32(w0.x); Ws[nxt][ldr   ][ldc+1]=f2tf32(w0.y);
            Ws[nxt][ldr   ][ldc+2]=f2tf32(w0.z); Ws[nxt][ldr   ][ldc+3]=f2tf32(w0.w);
            Ws[nxt][ldr+64][ldc+0]=f2tf32(w1.x); Ws[nxt][ldr+64][ldc+1]=f2tf32(w1.y);
            Ws[nxt][ldr+64][ldc+2]=f2tf32(w1.z); Ws[nxt][ldr+64][ldc+3]=f2tf32(w1.w);
        }
        __syncthreads();
    }

    // epilogue
    #pragma unroll
    for (int mi = 0; mi < 4; mi++) {
        #pragma unroll
        for (int ni = 0; ni < 4; ni++) {
            #pragma unroll
            for (int f = 0; f < 4; f++) {
                const int r = m0 + wm + (mi << 4) + grp + ((f >> 1) << 3);
                const int c = n0 + wn + (ni << 3) + (qk << 1) + (f & 1);
                float val = acc[mi][ni][f] + bias[c];
                if (EP == 1) val *= SCALING_;
                if (EP == 2) val = 0.5f * val * (1.0f + erff(val * 0.70710678118654752f));
                if (EP == 3) val += res[(size_t)r * N + c];
                C[(size_t)r * N + c] = val;
            }
        }
    }
}

// ---------------- RoPE (interleaved pairs), in-place -------------------------
__global__ void rope_kernel(float* __restrict__ t, const float* __restrict__ freqs, int npairs) {
    int idx = blockIdx.x * blockDim.x + threadIdx.x;
    if (idx >= npairs) return;
    const int row = idx / (D_ / 2);
    const int p   = idx - row * (D_ / 2);
    const int i   = p & 31;
    const int n   = row & (N_ - 1);
    const float ang = (float)n * freqs[i];
    const float c = cosf(ang), s = sinf(ang);
    float* base = t + (size_t)row * D_ + p * 2;
    const float x0 = base[0], x1 = base[1];
    base[0] = x0 * c - x1 * s;
    base[1] = x1 * c + x0 * s;
}

// ---------------- flash attention, fp32, BQ=64 BK=32 -------------------------
__device__ __forceinline__ float rmax16(float v) {
    #pragma unroll
    for (int o = 8; o; o >>= 1) v = fmaxf(v, __shfl_xor_sync(0xffffffffu, v, o, 16));
    return v;
}
__device__ __forceinline__ float rsum16(float v) {
    #pragma unroll
    for (int o = 8; o; o >>= 1) v += __shfl_xor_sync(0xffffffffu, v, o, 16);
    return v;
}

__global__ __launch_bounds__(256)
void attn_kernel(const float* __restrict__ q, const float* __restrict__ k,
                 const float* __restrict__ v, const unsigned char* __restrict__ pm,
                 float* __restrict__ out) {
    __shared__ float Qs[64][65];
    __shared__ float Ks[64][33];
    __shared__ float Vs[32][68];
    __shared__ float Ps[64][33];
    __shared__ unsigned char Ms[32];

    const int tid = threadIdx.x;
    const int tx = tid & 15, ty = tid >> 4;
    const int qt = blockIdx.x, bh = blockIdx.y;
    const int b = bh / H_, h = bh - b * H_;
    const int row0 = b * N_ + qt * 64;
    const int colh = h * HD_;

    for (int idx = tid; idx < 64 * 64; idx += 256) {
        const int r = idx >> 6, d = idx & 63;
        Qs[d][r] = q[(size_t)(row0 + r) * D_ + colh + d];
    }

    float o[4][4];
    #pragma unroll
    for (int i = 0; i < 4; i++)
        #pragma unroll
        for (int j = 0; j < 4; j++) o[i][j] = 0.f;
    float mreg[4], lreg[4];
    #pragma unroll
    for (int i = 0; i < 4; i++) { mreg[i] = -3.0e38f; lreg[i] = 0.f; }

    const int r0  = ty << 2;
    const int c0s = tx << 1;
    const int c0o = tx << 2;

    for (int kt = 0; kt < N_; kt += 32) {
        for (int idx = tid; idx < 32 * 64; idx += 256) {
            const int c = idx >> 6, d = idx & 63;
            const size_t g = (size_t)(b * N_ + kt + c) * D_ + colh + d;
            Ks[d][c] = k[g];
            Vs[c][d] = v[g];
        }
        if (tid < 32) Ms[tid] = pm[b * N_ + kt + tid];
        __syncthreads();

        float s[4][2];
        s[0][0]=s[0][1]=s[1][0]=s[1][1]=s[2][0]=s[2][1]=s[3][0]=s[3][1]=0.f;
        #pragma unroll 4
        for (int d = 0; d < 64; d++) {
            const float a0 = Qs[d][r0], a1 = Qs[d][r0+1], a2 = Qs[d][r0+2], a3 = Qs[d][r0+3];
            const float b0 = Ks[d][c0s], b1 = Ks[d][c0s+1];
            s[0][0] = fmaf(a0, b0, s[0][0]); s[0][1] = fmaf(a0, b1, s[0][1]);
            s[1][0] = fmaf(a1, b0, s[1][0]); s[1][1] = fmaf(a1, b1, s[1][1]);
            s[2][0] = fmaf(a2, b0, s[2][0]); s[2][1] = fmaf(a2, b1, s[2][1]);
            s[3][0] = fmaf(a3, b0, s[3][0]); s[3][1] = fmaf(a3, b1, s[3][1]);
        }
        const bool msk0 = Ms[c0s] != 0, msk1 = Ms[c0s+1] != 0;
        #pragma unroll
        for (int i = 0; i < 4; i++) {
            s[i][0] = msk0 ? -3.0e38f : s[i][0] * 0.125f;
            s[i][1] = msk1 ? -3.0e38f : s[i][1] * 0.125f;
        }

        #pragma unroll
        for (int i = 0; i < 4; i++) {
            float mt = rmax16(fmaxf(s[i][0], s[i][1]));
            const float mnew = fmaxf(mreg[i], mt);
            const float alpha = __expf(mreg[i] - mnew);
            const float p0 = __expf(s[i][0] - mnew);
            const float p1 = __expf(s[i][1] - mnew);
            const float rs = rsum16(p0 + p1);
            lreg[i] = lreg[i] * alpha + rs;
            mreg[i] = mnew;
            #pragma unroll
            for (int j = 0; j < 4; j++) o[i][j] *= alpha;
            Ps[r0 + i][c0s]     = p0;
            Ps[r0 + i][c0s + 1] = p1;
        }
        __syncthreads();

        #pragma unroll 4
        for (int kk = 0; kk < 32; kk++) {
            const float4 vv = *(const float4*)&Vs[kk][c0o];
            const float p0 = Ps[r0][kk],   p1 = Ps[r0+1][kk];
            const float p2 = Ps[r0+2][kk], p3 = Ps[r0+3][kk];
            o[0][0] = fmaf(p0, vv.x, o[0][0]); o[0][1] = fmaf(p0, vv.y, o[0][1]);
            o[0][2] = fmaf(p0, vv.z, o[0][2]); o[0][3] = fmaf(p0, vv.w, o[0][3]);
            o[1][0] = fmaf(p1, vv.x, o[1][0]); o[1][1] = fmaf(p1, vv.y, o[1][1]);
            o[1][2] = fmaf(p1, vv.z, o[1][2]); o[1][3] = fmaf(p1, vv.w, o[1][3]);
            o[2][0] = fmaf(p2, vv.x, o[2][0]); o[2][1] = fmaf(p2, vv.y, o[2][1]);
            o[2][2] = fmaf(p2, vv.z, o[2][2]); o[2][3] = fmaf(p2, vv.w, o[2][3]);
            o[3][0] = fmaf(p3, vv.x, o[3][0]); o[3][1] = fmaf(p3, vv.y, o[3][1]);
            o[3][2] = fmaf(p3, vv.z, o[3][2]); o[3][3] = fmaf(p3, vv.w, o[3][3]);
        }
        __syncthreads();
    }

    #pragma unroll
    for (int i = 0; i < 4; i++) {
        const float inv = 1.0f / lreg[i];
        float4 r4;
        r4.x = o[i][0] * inv; r4.y = o[i][1] * inv;
        r4.z = o[i][2] * inv; r4.w = o[i][3] * inv;
        *(float4*)&out[(size_t)(row0 + r0 + i) * D_ + colh + c0o] = r4;
    }
}

// ---------------- launch ------------------------------------------------------
extern "C" void kernel_launch(void* const* d_in, const int* in_sizes, int n_in,
                              void* d_out, int out_size) {
    const float* x     = (const float*)d_in[0];
    const unsigned char* pmask = (const unsigned char*)d_in[1];
    const float* wq = (const float*)d_in[2];
    const float* bq = (const float*)d_in[3];
    const float* wk = (const float*)d_in[4];
    const float* bk = (const float*)d_in[5];
    const float* wv = (const float*)d_in[6];
    const float* bv = (const float*)d_in[7];
    const float* wo = (const float*)d_in[8];
    const float* bo = (const float*)d_in[9];
    const float* w1 = (const float*)d_in[10];
    const float* b1 = (const float*)d_in[11];
    const float* w2 = (const float*)d_in[12];
    const float* b2 = (const float*)d_in[13];
    const float* ln1w = (const float*)d_in[14];
    const float* ln1b = (const float*)d_in[15];
    const float* ln2w = (const float*)d_in[16];
    const float* ln2b = (const float*)d_in[17];
    const float* freqs = (const float*)d_in[18];
    float* out = (float*)d_out;

    float *ph, *pq, *pk, *pv, *patt, *pff;
    cudaGetSymbolAddress((void**)&ph,   g_h);
    cudaGetSymbolAddress((void**)&pq,   g_q);
    cudaGetSymbolAddress((void**)&pk,   g_k);
    cudaGetSymbolAddress((void**)&pv,   g_v);
    cudaGetSymbolAddress((void**)&patt, g_att);
    cudaGetSymbolAddress((void**)&pff,  g_ff);

    const dim3 gD(D_ / 128, M_ / 128);     // (6, 64)
    const dim3 gF(FF_ / 128, M_ / 128);    // (24, 64)

    // LN1
    ln_kernel<<<M_, 256>>>(x, ln1w, ln1b, ph);
    // QKV projections (tf32 tensor cores)
    gemm_tf32<1><<<gD, 256>>>(ph, wq, bq, nullptr, pq, M_, D_, D_);
    gemm_tf32<0><<<gD, 256>>>(ph, wk, bk, nullptr, pk, M_, D_, D_);
    gemm_tf32<0><<<gD, 256>>>(ph, wv, bv, nullptr, pv, M_, D_, D_);
    // RoPE on q and k
    const int npairs = M_ * (D_ / 2);
    rope_kernel<<<(npairs + 255) / 256, 256>>>(pq, freqs, npairs);
    rope_kernel<<<(npairs + 255) / 256, 256>>>(pk, freqs, npairs);
    // attention
    attn_kernel<<<dim3(N_ / 64, B_ * H_), 256>>>(pq, pk, pv, pmask, patt);
    // O projection + residual (x) -> d_out
    gemm_tf32<3><<<gD, 256>>>(patt, wo, bo, x, out, M_, D_, D_);
    // LN2 (reuse g_h)
    ln_kernel<<<M_, 256>>>(out, ln2w, ln2b, ph);
    // FFN1 with exact GELU
    gemm_tf32<2><<<gF, 256>>>(ph, w1, b1, nullptr, pff, M_, FF_, D_);
    // FFN2 + residual (d_out) -> d_out
    gemm_tf32<3><<<gD, 256>>>(pff, w2, b2, out, out, M_, D_, FF_);
}